// round 17
// baseline (speedup 1.0000x reference)
#include <cuda_runtime.h>
#include <cstdint>
#include <cstddef>

#define N_SAMPLES 1024
#define IN_F      512
#define OUT_F     512
#define N_HEADS   32
#define N_SPLITS  4
#define N_COMBOS  (N_HEADS * N_SPLITS)
#define DELTA_SCALE 0.1f
#define K_SLICES  4
#define K_SLICE   (IN_F / K_SLICES)      // 128
#define COL_TILES (OUT_F / 256)          // 2

// ---------------------------------------------------------------------------
// Device scratch (no cudaMalloc allowed anywhere)
// ---------------------------------------------------------------------------
__device__ float g_partial[K_SLICES][N_SAMPLES * OUT_F]; // 8 MB k-slice partials
__device__ int   g_done[N_COMBOS * COL_TILES];           // arrival counters
                                                         // (0 at load; each use
                                                         //  cycles 0->4->0)

// ---------------------------------------------------------------------------
// Packed-pair fp32x2 FMA (SASS FFMA2 — only reachable via PTX fma.rn.f32x2)
// ---------------------------------------------------------------------------
#define FMA2(d, a, b, c) \
    asm("fma.rn.f32x2 %0, %1, %2, %3;" : "=l"(d) : "l"(a), "l"(b), "l"(c))
#define PACK2(d, s) \
    asm("mov.b64 %0, {%1, %1};" : "=l"(d) : "f"(s))

// ---------------------------------------------------------------------------
// Per-slice compute: thread owns 2 adjacent columns (c, c+1); accumulates
// R_PAIRS row-pairs over 128 local k with a 4k-ahead float2 prefetch of W/DW.
// DW is loaded with __ldcs (evict-first): 128 MB of zero-reuse stream must
// not evict the 4x-reused W slices from L2.
// x_s layout: pair rp, local k -> { x[2rp][k], x[2rp+1][k] } interleaved so a
// single LDS.128 yields two packed b64 FFMA2 operands (broadcast, no conflict).
// NOTE: x_s MUST be 16-byte aligned — accessed via ulonglong2 (LDS.128).
// ---------------------------------------------------------------------------
template <int R_PAIRS>
__device__ __forceinline__ void compute_slice(const float* __restrict__ Wc,
                                              const float* __restrict__ Dc,
                                              const float* x_s,
                                              const int*   s_idx,
                                              float* __restrict__ partial,
                                              int c) {
    unsigned long long acc0[R_PAIRS], acc1[R_PAIRS];   // col c / col c+1
#pragma unroll
    for (int rp = 0; rp < R_PAIRS; ++rp) { acc0[rp] = 0ull; acc1[rp] = 0ull; }

    float2 wb[2][4], db[2][4];
#pragma unroll
    for (int j = 0; j < 4; ++j) {
        wb[0][j] = *reinterpret_cast<const float2*>(Wc + (size_t)j * OUT_F);
        db[0][j] = __ldcs(reinterpret_cast<const float2*>(Dc + (size_t)j * OUT_F));
    }

#pragma unroll 2
    for (int kb = 0; kb < K_SLICE; kb += 4) {
        const int cur = (kb >> 2) & 1;
        const int nxt = cur ^ 1;
        const int kp  = (kb + 4) & (K_SLICE - 1);   // wraps last iter (unused)
#pragma unroll
        for (int j = 0; j < 4; ++j) {
            wb[nxt][j] = *reinterpret_cast<const float2*>(Wc + (size_t)(kp + j) * OUT_F);
            db[nxt][j] = __ldcs(reinterpret_cast<const float2*>(Dc + (size_t)(kp + j) * OUT_F));
        }

#pragma unroll
        for (int j = 0; j < 4; j += 2) {            // k-pair (kb+j, kb+j+1)
            const float wa0 = fmaf(DELTA_SCALE, db[cur][j].x,     wb[cur][j].x);
            const float wa1 = fmaf(DELTA_SCALE, db[cur][j].y,     wb[cur][j].y);
            const float wb0 = fmaf(DELTA_SCALE, db[cur][j + 1].x, wb[cur][j + 1].x);
            const float wb1 = fmaf(DELTA_SCALE, db[cur][j + 1].y, wb[cur][j + 1].y);
            unsigned long long a0, a1, b0, b1;
            PACK2(a0, wa0); PACK2(a1, wa1); PACK2(b0, wb0); PACK2(b1, wb1);
#pragma unroll
            for (int rp = 0; rp < R_PAIRS; ++rp) {
                const ulonglong2 xv = *reinterpret_cast<const ulonglong2*>(
                    &x_s[rp * (2 * K_SLICE) + 2 * (kb + j)]);
                FMA2(acc0[rp], xv.x, a0, acc0[rp]);
                FMA2(acc1[rp], xv.x, a1, acc1[rp]);
                FMA2(acc0[rp], xv.y, b0, acc0[rp]);
                FMA2(acc1[rp], xv.y, b1, acc1[rp]);
            }
        }
    }

#pragma unroll
    for (int rp = 0; rp < R_PAIRS; ++rp) {
        float lo0, hi0, lo1, hi1;
        asm("mov.b64 {%0, %1}, %2;" : "=f"(lo0), "=f"(hi0) : "l"(acc0[rp]));
        asm("mov.b64 {%0, %1}, %2;" : "=f"(lo1), "=f"(hi1) : "l"(acc1[rp]));
        const int s0 = s_idx[2 * rp];
        const int s1 = s_idx[2 * rp + 1];
        if (s0 >= 0)
            *reinterpret_cast<float2*>(&partial[s0 * OUT_F + c]) =
                make_float2(lo0, lo1);
        if (s1 >= 0)
            *reinterpret_cast<float2*>(&partial[s1 * OUT_F + c]) =
                make_float2(hi0, hi1);
    }
}

// ---------------------------------------------------------------------------
// Fused grouped kernel: self-grouping + k-split + FUSED REDUCTION EPILOGUE.
//   Grid: (128 combos, 2 col-tiles of 256, 4 k-slices of 128); 128 threads.
//   Prologue: warp-ballot ordered compaction of the samples matching this
//   block's combo (deterministic: sample-index order).
//   Mainloop: stream W/DW [128k x 256c] once, FFMA2 row-pairs, write k-slice
//   partials.
//   Epilogue: the 4 slice-blocks of a (combo, tile) group arrive on a
//   counter (threadfence + atomicAdd); the LAST one sums the 4 partials in
//   fixed slice order (deterministic), adds bias, writes out, and resets the
//   counter for the next graph replay.
// ---------------------------------------------------------------------------
__global__ void __launch_bounds__(128, 5)
fused_mm_kernel(const float* __restrict__ X,
                const float* __restrict__ W,
                const float* __restrict__ DW,
                const int* __restrict__ head_ix,
                const int* __restrict__ split_ix,
                const float* __restrict__ bias,
                float* __restrict__ out) {
    constexpr int R_TILE = 16;

    const int g = blockIdx.x;              // combo
    const int t = threadIdx.x;
    const int lane = t & 31;
    const int w    = t >> 5;               // warp id (0..3), owns samples [w*256, +256)

    // x_s FIRST and 16B-aligned: read with LDS.128 (ulonglong2). Misordering
    // smem decls off 16B alignment traps (R10 post-mortem).
    __shared__ __align__(16) float x_s[(R_TILE / 2) * 2 * K_SLICE];   // 8 KB
    __shared__ int   s_list[N_SAMPLES];    // 4 KB: this combo's samples, ordered
    __shared__ int   s_idx[R_TILE];
    __shared__ int   wcnt[4];
    __shared__ int   woff[8];              // 5 used; padded
    __shared__ int   is_last;

    // ---- ordered compaction of samples with combo == g ----
    bool hit[8];
#pragma unroll
    for (int r = 0; r < 8; ++r) {
        const int s = (w << 8) + (r << 5) + lane;
        hit[r] = (head_ix[s] * N_SPLITS + split_ix[s] == g);
    }
    unsigned masks[8];
    int mycnt = 0;
#pragma unroll
    for (int r = 0; r < 8; ++r) {
        masks[r] = __ballot_sync(0xFFFFFFFFu, hit[r]);
        mycnt += __popc(masks[r]);
    }
    if (lane == 0) wcnt[w] = mycnt;
    __syncthreads();
    if (t == 0) {
        int s = 0;
#pragma unroll
        for (int i = 0; i < 4; ++i) { woff[i] = s; s += wcnt[i]; }
        woff[4] = s;
    }
    __syncthreads();
    {
        int off = woff[w];
#pragma unroll
        for (int r = 0; r < 8; ++r) {
            if (hit[r]) {
                const int pos = off + __popc(masks[r] & ((1u << lane) - 1u));
                s_list[pos] = (w << 8) + (r << 5) + lane;
            }
            off += __popc(masks[r]);
        }
    }
    __syncthreads();
    const int count = woff[4];
    if (count == 0) return;   // no rows: no partials, no output, no counter use

    // ---- mainloop ----
    const int head = g >> 2;
    const int c    = blockIdx.y * 256 + 2 * t;
    const int k0   = blockIdx.z * K_SLICE;

    const float* __restrict__ Wc = W  + (size_t)head * (IN_F * OUT_F) + (size_t)k0 * OUT_F + c;
    const float* __restrict__ Dc = DW + (size_t)g    * (IN_F * OUT_F) + (size_t)k0 * OUT_F + c;
    float* __restrict__ partial = g_partial[blockIdx.z];

    for (int r0 = 0; r0 < count; r0 += R_TILE) {
        const int rows = min(R_TILE, count - r0);
        if (t < R_TILE) s_idx[t] = (t < rows) ? s_list[r0 + t] : -1;
        __syncthreads();

        const int pairs = (rows <= 4) ? 2 : (rows <= 8) ? 4 : 8;
        const int fill  = pairs * 2 * K_SLICE;

        for (int idx = t; idx < fill; idx += 128) {
            const int r = idx >> 7;              // idx / K_SLICE
            const int k = idx & (K_SLICE - 1);
            const int s = s_idx[r];
            x_s[(r >> 1) * (2 * K_SLICE) + 2 * k + (r & 1)] =
                (s >= 0) ? X[s * IN_F + k0 + k] : 0.0f;
        }
        __syncthreads();

        if (pairs == 2)
            compute_slice<2>(Wc, Dc, x_s, s_idx, partial, c);
        else if (pairs == 4)
            compute_slice<4>(Wc, Dc, x_s, s_idx, partial, c);
        else
            compute_slice<8>(Wc, Dc, x_s, s_idx, partial, c);
        __syncthreads();   // protect x_s / s_idx before next chunk
    }

    // ---- fused reduction epilogue (last slice-block of this (combo,tile)) --
    __threadfence();               // all threads: publish partial stores to L2
    __syncthreads();
    if (t == 0) {
        const int slot = g * COL_TILES + blockIdx.y;
        const int prev = atomicAdd(&g_done[slot], 1);
        is_last = (prev == K_SLICES - 1);
        if (is_last) g_done[slot] = 0;   // reset for next graph replay
    }
    __syncthreads();
    if (!is_last) return;

    // Deterministic: fixed slice order, independent of arrival order.
    const float2 bv = *reinterpret_cast<const float2*>(&bias[head * OUT_F + c]);
    for (int r = 0; r < count; ++r) {
        const size_t o = (size_t)s_list[r] * OUT_F + c;
        const float2 p0 = __ldcg(reinterpret_cast<const float2*>(&g_partial[0][o]));
        const float2 p1 = __ldcg(reinterpret_cast<const float2*>(&g_partial[1][o]));
        const float2 p2 = __ldcg(reinterpret_cast<const float2*>(&g_partial[2][o]));
        const float2 p3 = __ldcg(reinterpret_cast<const float2*>(&g_partial[3][o]));
        float2 r2;
        r2.x = ((p0.x + p1.x) + (p2.x + p3.x)) + bv.x;
        r2.y = ((p0.y + p1.y) + (p2.y + p3.y)) + bv.y;
        *reinterpret_cast<float2*>(&out[o]) = r2;
    }
}

// ---------------------------------------------------------------------------
// kernel_launch: inputs in metadata order
//   0 input f32[1024,512]  1 head_ix i32[1024]  2 split_ix i32[1024]
//   3 weight f32[32,512,512]  4 delta_weight f32[128,512,512]  5 bias f32[32,512]
// ---------------------------------------------------------------------------
extern "C" void kernel_launch(void* const* d_in, const int* in_sizes, int n_in,
                              void* d_out, int out_size) {
    const float* X    = (const float*)d_in[0];
    const int*   hix  = (const int*)d_in[1];
    const int*   six  = (const int*)d_in[2];
    const float* W    = (const float*)d_in[3];
    const float* DW   = (const float*)d_in[4];
    const float* bias = (const float*)d_in[5];

    for (int i = 0; i < n_in; ++i) {
        switch (in_sizes[i]) {
            case N_SAMPLES * IN_F:        X    = (const float*)d_in[i]; break;
            case N_HEADS * IN_F * OUT_F:  W    = (const float*)d_in[i]; break;
            case N_COMBOS * IN_F * OUT_F: DW   = (const float*)d_in[i]; break;
            case N_HEADS * OUT_F:         bias = (const float*)d_in[i]; break;
            default: break; // head_ix / split_ix keep metadata positions
        }
    }

    float* out = (float*)d_out;

    // ONE kernel: 128 combos x 2 col-tiles x 4 k-slices = 1024 blocks.
    // Grouping, GEMV, and cross-slice reduction all fused.
    fused_mm_kernel<<<dim3(N_COMBOS, COL_TILES, K_SLICES), 128>>>(
        X, W, DW, hix, six, bias, out);
}